// round 10
// baseline (speedup 1.0000x reference)
#include <cuda_runtime.h>
#include <cuda_bf16.h>
#include <cstdint>

// Problem constants (fixed by the reference generator).
#define NN   4096      // nodes
#define BB   2048      // batch
#define LL   128       // latent
#define KK   16        // max fan-in
#define DW   145       // 1 + LL + KK  (weights row length)
#define GKK  129       // 1 + LL       (GEMM K dim)

#define NE      14     // batch elements per CTA (147 CTAs -> one wave)
#define STRIDE  4097   // per-element smem stride: bank = (el + p) mod 32
#define NWP     8      // dataflow warps per CTA
#define PAD     48     // meta/pre pad rows (prefetch overrun: i+32 max)

#define STATE_F (NE * STRIDE)                     // 57,358 floats of chain state
#define SMEM_CHAIN_BYTES ((STATE_F + 16) * 4)     // + watermark[8] + pad = 229,496 B

// ---------------------------------------------------------------------------
// Scratch (__device__ globals zero-initialized at load; rows >= NN are never
// written by any kernel, so prefetch overruns read zeros -> parent 0, w 0).
// ---------------------------------------------------------------------------
__device__ float        g_pre[(NN + PAD) * BB];   // pre[i*BB+b] = bias + z[b].wz[i]
__device__ unsigned int g_meta[(NN + PAD) * 32];  // per node: 16 raw parent idx + 16 w bits

// ---------------------------------------------------------------------------
// Kernel 0: probe (shifts ncu's -s 5 capture slot toward chain_kernel).
// ---------------------------------------------------------------------------
__global__ void probe_kernel()
{
    if (threadIdx.x == 0) g_pre[(size_t)(NN + PAD) * BB - 1] = 0.0f;
}

// ---------------------------------------------------------------------------
// Kernel 1: pack per-node metadata: one 128B line = 16 parents + 16 weights.
// ---------------------------------------------------------------------------
__global__ void pack_meta_kernel(const float* __restrict__ w,
                                 const int*   __restrict__ par)
{
    const int wid = threadIdx.x >> 5;
    const int k   = threadIdx.x & 31;
    const int i   = blockIdx.x * 8 + wid;
    if (i >= NN) return;

    unsigned int v;
    if (k < 16)
        v = (unsigned int)par[i * KK + k];          // raw parent (pads = 0)
    else
        v = __float_as_uint(w[i * DW + (1 + LL) + (k - 16)]);  // pre-masked
    g_meta[i * 32 + k] = v;
}

// ---------------------------------------------------------------------------
// Kernel 2: pre[i][b] = sum_{k=0}^{128} w[i][k] * base[b][k],  base=[1, z].
// ---------------------------------------------------------------------------
#define G_PAD 68
__global__ void gemm_pre_kernel(const float* __restrict__ z,
                                const float* __restrict__ w)
{
    extern __shared__ float smg[];
    float* As = smg;
    float* Zs = smg + GKK * G_PAD;

    const int i0 = blockIdx.y * 64;
    const int b0 = blockIdx.x * 64;
    const int tid = threadIdx.x;

    for (int idx = tid; idx < 64 * GKK; idx += 256) {
        int r = idx / GKK, k = idx - r * GKK;
        As[k * G_PAD + r] = w[(i0 + r) * DW + k];
    }
    for (int idx = tid; idx < 64 * GKK; idx += 256) {
        int c = idx / GKK, k = idx - c * GKK;
        Zs[k * G_PAD + c] = (k == 0) ? 1.0f : z[(b0 + c) * LL + (k - 1)];
    }
    __syncthreads();

    const int tx = tid & 15;
    const int ty = tid >> 4;
    const int ri = ty * 4, ci = tx * 4;

    float acc[4][4];
#pragma unroll
    for (int r = 0; r < 4; r++)
#pragma unroll
        for (int c = 0; c < 4; c++) acc[r][c] = 0.0f;

#pragma unroll 3
    for (int k = 0; k < GKK; k++) {
        float4 a  = *reinterpret_cast<const float4*>(&As[k * G_PAD + ri]);
        float4 zc = *reinterpret_cast<const float4*>(&Zs[k * G_PAD + ci]);
        float av[4] = {a.x, a.y, a.z, a.w};
        float zv[4] = {zc.x, zc.y, zc.z, zc.w};
#pragma unroll
        for (int r = 0; r < 4; r++)
#pragma unroll
            for (int c = 0; c < 4; c++)
                acc[r][c] = fmaf(av[r], zv[c], acc[r][c]);
    }

#pragma unroll
    for (int r = 0; r < 4; r++) {
        float4 o = make_float4(acc[r][0], acc[r][1], acc[r][2], acc[r][3]);
        *reinterpret_cast<float4*>(&g_pre[(size_t)(i0 + ri + r) * BB + b0 + ci]) = o;
    }
}

// ---------------------------------------------------------------------------
// Kernel 3: DATAFLOW chain. 8 warps; warp w owns nodes {w, w+8, ...} in
// order. Readiness: lane k<16 holds parent p_k (strided load from the meta
// line) and spins on watermark[p_k & 7] >= p_k (ld.acquire; owner warp
// completes in index order, so the check is exact). Deadlock-free: the
// minimal incomplete node's parents are all complete, so its warp proceeds.
// After storing u[i] (lanes 0-13), __syncwarp + lane0 st.release publishes
// watermark[w] = i. Meta/pre prefetched depth-4 in registers (sequential
// stream, no indirection). No barriers, no serial tanh chain.
// ---------------------------------------------------------------------------
__global__ void __launch_bounds__(32 * NWP, 1)
chain_kernel(float* __restrict__ out)
{
    extern __shared__ float sm[];
    const int tid  = threadIdx.x;
    const int warp = tid >> 5;
    const int lane = tid & 31;
    const int b0   = blockIdx.x * NE;

    // Zero chain state; init watermarks to -1.
    for (int j = tid; j < STATE_F; j += 32 * NWP) sm[j] = 0.0f;
    if (tid < NWP) reinterpret_cast<int*>(sm + STATE_F)[tid] = -1;
    __syncthreads();

    {
        const int  elc = lane < 14 ? lane : 13;    // lanes 14-31 mirror el 13
        const bool so  = (lane < 14);
        int b = b0 + elc; if (b >= BB) b = BB - 1;
        char* __restrict__ ub = reinterpret_cast<char*>(sm + elc * STRIDE);
        const unsigned wmk_base = (unsigned)__cvta_generic_to_shared(sm + STATE_F);

        // Depth-4 register prefetch of the warp's meta/pre stream.
        int4   P[4][4];
        float4 W[4][4];
        float  pre[4];
        int    ps[4];                               // this lane's parent (strided)

        const int4*   mp = reinterpret_cast<const int4*>(g_meta);
        const float4* mw = reinterpret_cast<const float4*>(g_meta);
        const int*    mi = reinterpret_cast<const int*>(g_meta);

#pragma unroll
        for (int d = 0; d < 4; d++) {
            const int i = warp + d * NWP;
#pragma unroll
            for (int q = 0; q < 4; q++) P[d][q] = __ldg(mp + (size_t)i * 8 + q);
#pragma unroll
            for (int q = 0; q < 4; q++) W[d][q] = __ldg(mw + (size_t)i * 8 + 4 + q);
            ps[d]  = __ldg(mi + (size_t)i * 32 + (lane & 15));
            pre[d] = __ldg(g_pre + (size_t)i * BB + b);
        }

        int t = 0;
#pragma unroll 1
        for (int i = warp; i < NN; i += NWP, t++) {
            const int d = t & 3;

            // 1. readiness poll (exact, per parent). Node 0 has no parents.
            if (i != 0) {
                const int p = ps[d];
                const unsigned wa = wmk_base + ((unsigned)(p & 7) << 2);
                int done;
#pragma unroll 1
                do {
                    int wv;
                    asm volatile("ld.acquire.cta.shared::cta.b32 %0, [%1];"
                                 : "=r"(wv) : "r"(wa));
                    done = (wv >= p);
                } while (!__all_sync(0xffffffffu, done));
            }

            // 2. gathers (parents strictly precede; values published)
            int4 p0 = P[d][0], p1 = P[d][1], p2 = P[d][2], p3 = P[d][3];
            float g0  = *reinterpret_cast<const float*>(ub + 4 * p0.x);
            float g1  = *reinterpret_cast<const float*>(ub + 4 * p0.y);
            float g2  = *reinterpret_cast<const float*>(ub + 4 * p0.z);
            float g3  = *reinterpret_cast<const float*>(ub + 4 * p0.w);
            float g4  = *reinterpret_cast<const float*>(ub + 4 * p1.x);
            float g5  = *reinterpret_cast<const float*>(ub + 4 * p1.y);
            float g6  = *reinterpret_cast<const float*>(ub + 4 * p1.z);
            float g7  = *reinterpret_cast<const float*>(ub + 4 * p1.w);
            float g8  = *reinterpret_cast<const float*>(ub + 4 * p2.x);
            float g9  = *reinterpret_cast<const float*>(ub + 4 * p2.y);
            float g10 = *reinterpret_cast<const float*>(ub + 4 * p2.z);
            float g11 = *reinterpret_cast<const float*>(ub + 4 * p2.w);
            float g12 = *reinterpret_cast<const float*>(ub + 4 * p3.x);
            float g13 = *reinterpret_cast<const float*>(ub + 4 * p3.y);
            float g14 = *reinterpret_cast<const float*>(ub + 4 * p3.z);
            float g15 = *reinterpret_cast<const float*>(ub + 4 * p3.w);

            // 3. dot
            float a0 = fmaf(g0,  W[d][0].x, pre[d]);
            float a1 = g1  * W[d][0].y;
            float a2 = g2  * W[d][0].z;
            float a3 = g3  * W[d][0].w;
            a0 = fmaf(g4,  W[d][1].x, a0);
            a1 = fmaf(g5,  W[d][1].y, a1);
            a2 = fmaf(g6,  W[d][1].z, a2);
            a3 = fmaf(g7,  W[d][1].w, a3);
            a0 = fmaf(g8,  W[d][2].x, a0);
            a1 = fmaf(g9,  W[d][2].y, a1);
            a2 = fmaf(g10, W[d][2].z, a2);
            a3 = fmaf(g11, W[d][2].w, a3);
            a0 = fmaf(g12, W[d][3].x, a0);
            a1 = fmaf(g13, W[d][3].y, a1);
            a2 = fmaf(g14, W[d][3].z, a2);
            a3 = fmaf(g15, W[d][3].w, a3);
            float s = (a0 + a1) + (a2 + a3);

            // 4. tanh(s) = 1 - 2/(exp(2s)+1); exact at saturation
            float e, r;
            asm("ex2.approx.f32 %0, %1;" : "=f"(e) : "f"(s * 2.885390082f));
            asm("rcp.approx.f32 %0, %1;" : "=f"(r) : "f"(e + 1.0f));
            float tv = fmaf(-2.0f, r, 1.0f);

            // 5. commit + publish
            if (so) *reinterpret_cast<float*>(ub + 4 * i) = tv;
            __syncwarp();
            if (lane == 0) {
                const unsigned wa = wmk_base + ((unsigned)warp << 2);
                asm volatile("st.release.cta.shared::cta.b32 [%0], %1;"
                             :: "r"(wa), "r"(i) : "memory");
            }

            // 6. refill prefetch slot d with node i + 4*NWP (padded arrays)
            {
                const int n = i + 4 * NWP;
#pragma unroll
                for (int q = 0; q < 4; q++) P[d][q] = __ldg(mp + (size_t)n * 8 + q);
#pragma unroll
                for (int q = 0; q < 4; q++) W[d][q] = __ldg(mw + (size_t)n * 8 + 4 + q);
                ps[d]  = __ldg(mi + (size_t)n * 32 + (lane & 15));
                pre[d] = __ldg(g_pre + (size_t)n * BB + b);
            }
        }
    }
    __syncthreads();

    // Cooperative coalesced dump: SMEM -> out[b*NN + i].
    for (int e = 0; e < NE; e++) {
        const int b = blockIdx.x * NE + e;
        if (b >= BB) break;
        const float* __restrict__ us = sm + e * STRIDE;
        for (int j = tid; j < NN; j += 32 * NWP)
            out[(size_t)b * NN + j] = us[j];
    }
}

// ---------------------------------------------------------------------------
// Launch. Inputs: z f32[2048,128], weights f32[4096,145],
// parent_mask f32[4096,16] (redundant — weights pre-masked), parents i32[4096,16].
// Output: f32[2048, 4096].
// ---------------------------------------------------------------------------
extern "C" void kernel_launch(void* const* d_in, const int* in_sizes, int n_in,
                              void* d_out, int out_size)
{
    const float* z       = (const float*)d_in[0];
    const float* weights = (const float*)d_in[1];
    const int*   parents = (const int*)d_in[3];
    float*       out     = (float*)d_out;

    const int gemm_smem  = 2 * GKK * G_PAD * (int)sizeof(float);   // 70,176 B
    const int chain_smem = SMEM_CHAIN_BYTES;                        // 229,496 B

    cudaFuncSetAttribute(gemm_pre_kernel,
                         cudaFuncAttributeMaxDynamicSharedMemorySize, gemm_smem);
    cudaFuncSetAttribute(chain_kernel,
                         cudaFuncAttributeMaxDynamicSharedMemorySize, chain_smem);

    probe_kernel<<<1, 32>>>();

    pack_meta_kernel<<<(NN + 7) / 8, 256>>>(weights, parents);

    dim3 ggrid(BB / 64, NN / 64);
    gemm_pre_kernel<<<ggrid, 256, gemm_smem>>>(z, weights);

    const int nblocks = (BB + NE - 1) / NE;   // 147
    chain_kernel<<<nblocks, 32 * NWP, chain_smem>>>(out);
}